// round 14
// baseline (speedup 1.0000x reference)
#include <cuda_runtime.h>
#include <cuda_bf16.h>
#include <math_constants.h>

// Problem constants (fixed by setup_inputs)
#define NPTS  16384
#define BATCH 8
#define M     2048
#define CH    128

#define CAP       3072               // per-batch bucket capacity (mean 2048, sd ~42)
#define CHUNK_PTS 16                 // points per block (8 warps x 2 points)
#define NCHUNKS   (CAP / CHUNK_PTS)  // 192
#define FULL 0xffffffffu

typedef unsigned long long ull;

// Device scratch (no allocs allowed)
__device__ float g_featsT[BATCH * M * CH];   // (B, m, C)
__device__ float g_ksoa[BATCH * 3 * M];      // coords SoA: [b][xyz][m]
__device__ int   g_bucket[BATCH * CAP];      // point ids grouped by batch
__device__ int   g_cnt[BATCH];               // per-batch counts

// ---------------------------------------------------------------------------
// f32x2 packed helpers. Per-lane results are bit-identical to the scalar
// FADD/FFMA chain (IEEE rn each half, same association).
// ---------------------------------------------------------------------------
__device__ __forceinline__ ull pack2(float lo, float hi) {
    ull r; asm("mov.b64 %0, {%1, %2};" : "=l"(r) : "f"(lo), "f"(hi)); return r;
}
__device__ __forceinline__ void unpack2(ull v, float& lo, float& hi) {
    asm("mov.b64 {%0, %1}, %2;" : "=f"(lo), "=f"(hi) : "l"(v));   // reg-pair alias, free
}
__device__ __forceinline__ ull add2(ull a, ull b) {
    ull r; asm("add.rn.f32x2 %0, %1, %2;" : "=l"(r) : "l"(a), "l"(b)); return r;
}
__device__ __forceinline__ ull mul2(ull a, ull b) {
    ull r; asm("mul.rn.f32x2 %0, %1, %2;" : "=l"(r) : "l"(a), "l"(b)); return r;
}
__device__ __forceinline__ ull fma2(ull a, ull b, ull c) {
    ull r; asm("fma.rn.f32x2 %0, %1, %2, %3;" : "=l"(r) : "l"(a), "l"(b), "l"(c)); return r;
}

// ---------------------------------------------------------------------------
// Fused: feats transpose (B,C,m)->(B,m,C), TWO 32x32 XOR-swizzled tiles per
// block (64-wide m tile, MLP=2)                          [z = 0..7]
//      + coord SoA split / counter zero                  [z = 8]
// ---------------------------------------------------------------------------
__global__ void __launch_bounds__(256)
transpose_prep_kernel(const float* __restrict__ feats,
                      const float* __restrict__ known)
{
    const int t = threadIdx.x;
    if (blockIdx.z < BATCH) {
        // element (c,j) of each tile at tile[c*8 + ((j>>2) ^ ((c>>2)&7))].comp(j&3)
        __shared__ float4 tileA[32 * 8];
        __shared__ float4 tileB[32 * 8];
        const int b  = blockIdx.z;
        const int j0 = blockIdx.x * 64;       // m tile (two 32-wide halves)
        const int c0 = blockIdx.y * 32;       // channel tile

        {   // load: thread t -> channel c = t>>3, float4-chunk m4 = t&7
            const int c  = t >> 3;
            const int m4 = t & 7;
            const float* rowp = &feats[((size_t)(b * CH + c0 + c)) * M + j0];
            const float4 vA = *(const float4*)&rowp[m4 * 4];
            const float4 vB = *(const float4*)&rowp[32 + m4 * 4];
            const int sw = c * 8 + (m4 ^ ((c >> 2) & 7));
            tileA[sw] = vA;
            tileB[sw] = vB;
        }
        __syncthreads();
        {   // store: thread t -> m row j = t>>3, channel-chunk q = t&7
            const int j = t >> 3;
            const int q = t & 7;
            const int col4 = j >> 2;
            const int comp = j & 3;
            const float* tfA = (const float*)tileA;
            const float* tfB = (const float*)tileB;
            float vA[4], vB[4];
            #pragma unroll
            for (int i = 0; i < 4; i++) {
                const int c = 4 * q + i;
                const int off = c * 32 + ((col4 ^ ((c >> 2) & 7)) * 4) + comp;
                vA[i] = tfA[off];
                vB[i] = tfB[off];
            }
            *(float4*)&g_featsT[((size_t)(b * M + j0 + j)) * CH + c0 + 4 * q] =
                make_float4(vA[0], vA[1], vA[2], vA[3]);
            *(float4*)&g_featsT[((size_t)(b * M + j0 + 32 + j)) * CH + c0 + 4 * q] =
                make_float4(vB[0], vB[1], vB[2], vB[3]);
        }
    } else {
        const int i = (blockIdx.x * gridDim.y + blockIdx.y) * 256 + t;  // 0..32767
        if (i < BATCH) g_cnt[i] = 0;
        if (i < BATCH * M) {
            const int b = i / M, j = i - b * M;
            g_ksoa[(b * 3 + 0) * M + j] = known[3 * i + 0];
            g_ksoa[(b * 3 + 1) * M + j] = known[3 * i + 1];
            g_ksoa[(b * 3 + 2) * M + j] = known[3 * i + 2];
        }
    }
}

// ---------------------------------------------------------------------------
// Bucket points by batch (order nondeterministic; output invariant to it).
// ---------------------------------------------------------------------------
__global__ void bucket_kernel(const int* __restrict__ batch_inds)
{
    __shared__ int hist[BATCH];
    __shared__ int base[BATCH];
    __shared__ int loc[BATCH];
    const int t = threadIdx.x;
    if (t < BATCH) { hist[t] = 0; loc[t] = 0; }
    __syncthreads();

    const int p = blockIdx.x * blockDim.x + t;
    const int b = batch_inds[p];
    atomicAdd(&hist[b], 1);
    __syncthreads();

    if (t < BATCH) base[t] = atomicAdd(&g_cnt[t], hist[t]);
    __syncthreads();

    const int r   = atomicAdd(&loc[b], 1);
    const int pos = base[b] + r;
    if (pos < CAP) g_bucket[b * CAP + pos] = p;
}

// ---------------------------------------------------------------------------
// Warp-collective EXACT top-3 update (REDUX loop, early-breaking).
// Candidate index of lane src is off + 4*src (monotone in src -> lowest
// owner lane = lowest index). Keys (d_bits << 32 | idx): uint order of
// non-negative floats is monotone; ties -> lower index (jax top_k).
// ---------------------------------------------------------------------------
__device__ __forceinline__ void topk_update(bool pass, float d, int off, int lane,
                                            ull& k0, ull& k1, ull& k2)
{
    unsigned cur = pass ? __float_as_uint(d) : 0xFFFFFFFFu;
    while (true) {
        const unsigned mind   = __reduce_min_sync(FULL, cur);
        const unsigned owners = __ballot_sync(FULL, cur == mind);
        const int      src    = __ffs(owners) - 1;      // lowest lane = lowest idx
        const ull      mkey   = ((ull)mind << 32) | (unsigned)(off + (src << 2));
        if (mkey >= k2) break;
        const bool b0 = mkey < k0, b1 = mkey < k1;
        k2 = b1 ? k1 : mkey;
        k1 = b0 ? k0 : (b1 ? mkey : k1);
        k0 = b0 ? mkey : k0;
        if (lane == src) cur = 0xFFFFFFFFu;             // consume winner
        if (!__any_sync(FULL, cur <= (unsigned)(k2 >> 32))) break;  // cheap pre-break
    }
}

// Weights + feature gather + output write for one finished point.
__device__ __forceinline__ void write_point(int pid, int b, ull k0, ull k1, ull k2,
                                            int lane, float* __restrict__ out)
{
    const float d0 = __uint_as_float((unsigned)(k0 >> 32));
    const float d1 = __uint_as_float((unsigned)(k1 >> 32));
    const float d2 = __uint_as_float((unsigned)(k2 >> 32));
    float w0 = 1.0f / (sqrtf(d0) + 1e-8f);
    float w1 = 1.0f / (sqrtf(d1) + 1e-8f);
    float w2 = 1.0f / (sqrtf(d2) + 1e-8f);
    const float inv = 1.0f / (w0 + w1 + w2);
    w0 *= inv; w1 *= inv; w2 *= inv;

    const int i0 = (int)(unsigned)k0;
    const int i1 = (int)(unsigned)k1;
    const int i2 = (int)(unsigned)k2;

    const float4 a0 = ((const float4*)(g_featsT + ((size_t)(b * M + i0)) * CH))[lane];
    const float4 a1 = ((const float4*)(g_featsT + ((size_t)(b * M + i1)) * CH))[lane];
    const float4 a2 = ((const float4*)(g_featsT + ((size_t)(b * M + i2)) * CH))[lane];
    float4 o;
    o.x = fmaf(w0, a0.x, fmaf(w1, a1.x, w2 * a2.x));
    o.y = fmaf(w0, a0.y, fmaf(w1, a1.y, w2 * a2.y));
    o.z = fmaf(w0, a0.z, fmaf(w1, a1.z, w2 * a2.z));
    o.w = fmaf(w0, a0.w, fmaf(w1, a1.w, w2 * a2.w));
    ((float4*)out)[(size_t)pid * (CH / 4) + lane] = o;
}

// ---------------------------------------------------------------------------
// Main: block = (chunk of 16 points, batch). One batch's 2048 coords in SoA
// smem (24KB). Each warp: 2 same-batch points; each lane: FOUR consecutive
// candidates per 128-candidate window via 3 LDS.128 (= 2 pre-packed f32x2
// operand pairs per coordinate). Packed distance math is bit-identical to
// the scalar chain. ONE vote per 128-candidate window (16 windows total);
// exact REDUX top-3 merge on triggering windows only.
// ---------------------------------------------------------------------------
__global__ void __launch_bounds__(256)
knn_main_kernel(const float* __restrict__ unknown, float* __restrict__ out)
{
    __shared__ __align__(16) float sco[3 * M];    // sx | sy | sz, 24 KB
    const int b     = blockIdx.y;
    const int cnt   = g_cnt[b];
    const int start = blockIdx.x * CHUNK_PTS;
    if (start >= cnt) return;                     // uniform exit, pre-sync

    const int t    = threadIdx.x;
    const int lane = t & 31;
    const int w    = t >> 5;

    // Point loads first so their latency overlaps the smem fill.
    int pidA = -1, pidB = -1;
    ull nxA = 0, nyA = 0, nzA = 0;
    ull nxB = 0, nyB = 0, nzB = 0;
    float t2A = -CUDART_INF_F, t2B = -CUDART_INF_F;   // inactive -> never passes

    const int ibA = start + w * 2;
    const int ibB = ibA + 1;
    if (ibA < cnt) {
        pidA = g_bucket[b * CAP + ibA];
        const float x = unknown[pidA * 3 + 0];
        const float y = unknown[pidA * 3 + 1];
        const float z = unknown[pidA * 3 + 2];
        nxA = pack2(-x, -x); nyA = pack2(-y, -y); nzA = pack2(-z, -z);
        t2A = CUDART_INF_F;
    }
    if (ibB < cnt) {
        pidB = g_bucket[b * CAP + ibB];
        const float x = unknown[pidB * 3 + 0];
        const float y = unknown[pidB * 3 + 1];
        const float z = unknown[pidB * 3 + 2];
        nxB = pack2(-x, -x); nyB = pack2(-y, -y); nzB = pack2(-z, -z);
        t2B = CUDART_INF_F;
    }

    {
        const float4* __restrict__ src4 = (const float4*)(g_ksoa + b * 3 * M);
        #pragma unroll
        for (int i = 0; i < 3 * M / 4 / 256; i++)
            ((float4*)sco)[t + 256 * i] = src4[t + 256 * i];
    }
    __syncthreads();

    const float* sx = sco;
    const float* sy = sco + M;
    const float* sz = sco + 2 * M;

    ull k0A = ~0ull, k1A = ~0ull, k2A = ~0ull;
    ull k0B = ~0ull, k1B = ~0ull, k2B = ~0ull;

    #pragma unroll 2
    for (int it = 0; it < M / 128; it++) {
        const int cb = it * 128 + 4 * lane;       // lane's candidates: cb .. cb+3
        // LDS.128 each: two packed f32x2 coordinate pairs per axis
        const uint4 xraw = *(const uint4*)&sx[cb];
        const uint4 yraw = *(const uint4*)&sy[cb];
        const uint4 zraw = *(const uint4*)&sz[cb];
        const ull cx12 = ((ull)xraw.y << 32) | xraw.x;
        const ull cx34 = ((ull)xraw.w << 32) | xraw.z;
        const ull cy12 = ((ull)yraw.y << 32) | yraw.x;
        const ull cy34 = ((ull)yraw.w << 32) | yraw.z;
        const ull cz12 = ((ull)zraw.y << 32) | zraw.x;
        const ull cz34 = ((ull)zraw.w << 32) | zraw.z;

        // packed distances: per-half identical to fmaf(dx,dx,fmaf(dy,dy,dz*dz))
        const ull dxA1 = add2(cx12, nxA), dyA1 = add2(cy12, nyA), dzA1 = add2(cz12, nzA);
        const ull ddA1 = fma2(dxA1, dxA1, fma2(dyA1, dyA1, mul2(dzA1, dzA1)));
        const ull dxA2 = add2(cx34, nxA), dyA2 = add2(cy34, nyA), dzA2 = add2(cz34, nzA);
        const ull ddA2 = fma2(dxA2, dxA2, fma2(dyA2, dyA2, mul2(dzA2, dzA2)));
        const ull dxB1 = add2(cx12, nxB), dyB1 = add2(cy12, nyB), dzB1 = add2(cz12, nzB);
        const ull ddB1 = fma2(dxB1, dxB1, fma2(dyB1, dyB1, mul2(dzB1, dzB1)));
        const ull dxB2 = add2(cx34, nxB), dyB2 = add2(cy34, nyB), dzB2 = add2(cz34, nzB);
        const ull ddB2 = fma2(dxB2, dxB2, fma2(dyB2, dyB2, mul2(dzB2, dzB2)));

        float dA1, dA2, dA3, dA4, dB1, dB2, dB3, dB4;
        unpack2(ddA1, dA1, dA2);                  // free (register-pair halves)
        unpack2(ddA2, dA3, dA4);
        unpack2(ddB1, dB1, dB2);
        unpack2(ddB2, dB3, dB4);

        const bool pA1 = dA1 <= t2A, pA2 = dA2 <= t2A, pA3 = dA3 <= t2A, pA4 = dA4 <= t2A;
        const bool pB1 = dB1 <= t2B, pB2 = dB2 <= t2B, pB3 = dB3 <= t2B, pB4 = dB4 <= t2B;

        const bool anyA = pA1 | pA2 | pA3 | pA4;
        const bool anyB = pB1 | pB2 | pB3 | pB4;

        if (__any_sync(FULL, anyA | anyB)) {
            const int base = it * 128;
            if (__any_sync(FULL, anyA)) {
                if (__any_sync(FULL, pA1)) topk_update(pA1, dA1, base,     lane, k0A, k1A, k2A);
                if (__any_sync(FULL, pA2)) topk_update(pA2, dA2, base + 1, lane, k0A, k1A, k2A);
                if (__any_sync(FULL, pA3)) topk_update(pA3, dA3, base + 2, lane, k0A, k1A, k2A);
                if (__any_sync(FULL, pA4)) topk_update(pA4, dA4, base + 3, lane, k0A, k1A, k2A);
                t2A = __uint_as_float((unsigned)(k2A >> 32));
            }
            if (__any_sync(FULL, anyB)) {
                if (__any_sync(FULL, pB1)) topk_update(pB1, dB1, base,     lane, k0B, k1B, k2B);
                if (__any_sync(FULL, pB2)) topk_update(pB2, dB2, base + 1, lane, k0B, k1B, k2B);
                if (__any_sync(FULL, pB3)) topk_update(pB3, dB3, base + 2, lane, k0B, k1B, k2B);
                if (__any_sync(FULL, pB4)) topk_update(pB4, dB4, base + 3, lane, k0B, k1B, k2B);
                t2B = __uint_as_float((unsigned)(k2B >> 32));
            }
        }
    }

    if (pidA >= 0) write_point(pidA, b, k0A, k1A, k2A, lane, out);
    if (pidB >= 0) write_point(pidB, b, k0B, k1B, k2B, lane, out);
}

// ---------------------------------------------------------------------------
extern "C" void kernel_launch(void* const* d_in, const int* in_sizes, int n_in,
                              void* d_out, int out_size)
{
    const float* unknown     = (const float*)d_in[0];
    const float* known       = (const float*)d_in[1];
    const int*   batch_inds  = (const int*)d_in[2];
    const float* known_feats = (const float*)d_in[3];
    float* out = (float*)d_out;

    transpose_prep_kernel<<<dim3(M / 64, CH / 32, BATCH + 1), 256>>>(known_feats, known);
    bucket_kernel<<<NPTS / 256, 256>>>(batch_inds);
    knn_main_kernel<<<dim3(NCHUNKS, BATCH), 256>>>(unknown, out);
}